// round 8
// baseline (speedup 1.0000x reference)
#include <cuda_runtime.h>

#define ND0 100000
#define ND1 10000
#define ND2 1024
#define E0C 1000000
#define E1C 100000
#define E2C 10240
#define DH  128
#define NCLS 47

// ---------------- scratch (device globals: allocation-free) ----------------
// NOTE: these symbols are referenced ONLY from device code. Passing them as
// kernel arguments from host code binds the host shadow symbol (silently
// dereferenceable on GB300 via ATS) — that was the all-zeros bug.
static __device__ int g_deg0[ND0];
static __device__ int g_indeg1[ND1];
static __device__ int g_outdeg1[ND0];
static __device__ int g_indeg2[ND2];
static __device__ int g_outdeg2[ND1];
static __device__ int g_off0[ND0 + 1];
static __device__ int g_off1[ND1 + 1];
static __device__ int g_off2[ND2 + 1];
static __device__ int g_csr0[E0C];
static __device__ int g_csr1[E1C];
static __device__ int g_csr2[E2C];
static __device__ float g_agg0[ND0 * DH];
static __device__ float g_h0[ND0 * DH];
static __device__ float g_agg1[ND1 * DH];
static __device__ float g_h1[ND1 * DH];
static __device__ float g_agg2[ND2 * DH];

// ---------------- counters zero ----------------
__global__ void zero_counts_kernel() {
    int i = blockIdx.x * blockDim.x + threadIdx.x;
    if (i < ND0) g_deg0[i] = 0;
    if (i < ND1) g_indeg1[i] = 0;
    if (i < ND0) g_outdeg1[i] = 0;
    if (i < ND2) g_indeg2[i] = 0;
    if (i < ND1) g_outdeg2[i] = 0;
}

// ---------------- histograms for all 3 layers ----------------
__global__ void hist_all_kernel(const int* __restrict__ src0, const int* __restrict__ dst0,
                                const int* __restrict__ src1, const int* __restrict__ dst1,
                                const int* __restrict__ src2, const int* __restrict__ dst2) {
    int i = blockIdx.x * blockDim.x + threadIdx.x;
    if (i < E0C) atomicAdd(&g_deg0[dst0[i]], 1);
    if (i < E1C) { atomicAdd(&g_indeg1[dst1[i]], 1); atomicAdd(&g_outdeg1[src1[i]], 1); }
    if (i < E2C) { atomicAdd(&g_indeg2[dst2[i]], 1); atomicAdd(&g_outdeg2[src2[i]], 1); }
}

// ---------------- single-block exclusive scan (4 elems/thread/iter) ----------------
__device__ void exscan_block(const int* __restrict__ deg, int* __restrict__ off, int n) {
    __shared__ int warp_sums[16];
    __shared__ int s_carry;
    const int T = 512;
    int tid = threadIdx.x, lane = tid & 31, w = tid >> 5;
    if (tid == 0) s_carry = 0;
    __syncthreads();
    for (int base = 0; base < n; base += T * 4) {
        int idx = base + tid * 4;
        int4 v = make_int4(0, 0, 0, 0);
        if (idx + 3 < n) v = *(const int4*)(deg + idx);
        else {
            if (idx     < n) v.x = deg[idx];
            if (idx + 1 < n) v.y = deg[idx + 1];
            if (idx + 2 < n) v.z = deg[idx + 2];
            if (idx + 3 < n) v.w = deg[idx + 3];
        }
        int s1 = v.x, s2 = s1 + v.y, s3 = s2 + v.z, s4 = s3 + v.w;
        int x = s4;
        #pragma unroll
        for (int d = 1; d < 32; d <<= 1) {
            int y = __shfl_up_sync(0xffffffffu, x, d);
            if (lane >= d) x += y;
        }
        if (lane == 31) warp_sums[w] = x;
        __syncthreads();
        if (w == 0 && lane < 16) {
            int s = warp_sums[lane];
            #pragma unroll
            for (int d = 1; d < 16; d <<= 1) {
                int y = __shfl_up_sync(0x0000ffffu, s, d);
                if (lane >= d) s += y;
            }
            warp_sums[lane] = s;
        }
        __syncthreads();
        int pre = s_carry + (w > 0 ? warp_sums[w - 1] : 0) + (x - s4);
        if (idx     < n) off[idx]     = pre;
        if (idx + 1 < n) off[idx + 1] = pre + s1;
        if (idx + 2 < n) off[idx + 2] = pre + s2;
        if (idx + 3 < n) off[idx + 3] = pre + s3;
        __syncthreads();
        if (tid == 0) s_carry += warp_sums[15];
        __syncthreads();
    }
    if (tid == 0) off[n] = s_carry;
}

__global__ void scan3_kernel() {
    if (blockIdx.x == 0)      exscan_block(g_deg0,   g_off0, ND0);
    else if (blockIdx.x == 1) exscan_block(g_indeg1, g_off1, ND1);
    else                      exscan_block(g_indeg2, g_off2, ND2);
}

// ---------------- CSR scatter ----------------
__global__ void scatter_all_kernel(const int* __restrict__ src0, const int* __restrict__ dst0,
                                   const int* __restrict__ src1, const int* __restrict__ dst1,
                                   const int* __restrict__ src2, const int* __restrict__ dst2) {
    int i = blockIdx.x * blockDim.x + threadIdx.x;
    if (i < E0C) {
        int d = dst0[i];
        int old = atomicSub(&g_deg0[d], 1);
        g_csr0[g_off0[d] + old - 1] = src0[i];
    }
    if (i < E1C) {
        int d = dst1[i];
        int old = atomicSub(&g_indeg1[d], 1);
        g_csr1[g_off1[d] + old - 1] = src1[i];
    }
    if (i < E2C) {
        int d = dst2[i];
        int old = atomicSub(&g_indeg2[d], 1);
        g_csr2[g_off2[d] + old - 1] = src2[i];
    }
}

// ---------------- layer 0 aggregation: one warp per dst node, float4 lanes ----------
__global__ void agg0_kernel(const float4* __restrict__ feats4) {
    int gid = blockIdx.x * blockDim.x + threadIdx.x;
    int node = gid >> 5;
    int lane = gid & 31;
    if (node >= ND0) return;
    int s = g_off0[node], e = g_off0[node + 1];
    float4 acc = make_float4(0.f, 0.f, 0.f, 0.f);
    for (int i = s; i < e; i++) {
        int u = g_csr0[i];
        float4 v = __ldg(&feats4[u * 32 + lane]);
        acc.x += v.x; acc.y += v.y; acc.z += v.z; acc.w += v.w;
    }
    ((float4*)g_agg0)[node * 32 + lane] = acc;
}

// ---------------- layer 1 aggregation: perm-folded gather + out-degree scale --------
__global__ void agg1_kernel(const int* __restrict__ inverse_idx,
                            const int* __restrict__ shuffle_idx) {
    int gid = blockIdx.x * blockDim.x + threadIdx.x;
    int node = gid >> 5;
    int lane = gid & 31;
    if (node >= ND1) return;
    int s = g_off1[node], e = g_off1[node + 1];
    float4 acc = make_float4(0.f, 0.f, 0.f, 0.f);
    for (int i = s; i < e; i++) {
        int u = g_csr1[i];
        int row = inverse_idx[shuffle_idx[u]];
        float sc = rsqrtf(fmaxf((float)g_outdeg1[u], 1.f));
        float4 v = ((const float4*)g_h0)[row * 32 + lane];
        acc.x += v.x * sc; acc.y += v.y * sc; acc.z += v.z * sc; acc.w += v.w * sc;
    }
    ((float4*)g_agg1)[node * 32 + lane] = acc;
}

// ---------------- layer 2 aggregation ----------------
__global__ void agg2_kernel() {
    int gid = blockIdx.x * blockDim.x + threadIdx.x;
    int node = gid >> 5;
    int lane = gid & 31;
    if (node >= ND2) return;
    int s = g_off2[node], e = g_off2[node + 1];
    float4 acc = make_float4(0.f, 0.f, 0.f, 0.f);
    for (int i = s; i < e; i++) {
        int u = g_csr2[i];
        float sc = rsqrtf(fmaxf((float)g_outdeg2[u], 1.f));
        float4 v = ((const float4*)g_h1)[u * 32 + lane];
        acc.x += v.x * sc; acc.y += v.y * sc; acc.z += v.z * sc; acc.w += v.w * sc;
    }
    ((float4*)g_agg2)[node * 32 + lane] = acc;
}

// ---------------- [N,128] @ [128,128] + bias (+ optional in-deg scale, relu) --------
// layer selector resolves device-global buffers IN DEVICE CODE (the fix).
// blockDim 256: 32 rows/block; each thread owns a 4x4 register tile.
// W staged in 32-row K-chunks (16KB) -> 32KB static smem total.
__global__ void mm128_kernel(const float* __restrict__ W, const float* __restrict__ bias,
                             int layer) {
    __shared__ float Ws[32 * 128];
    __shared__ float As[32 * 128];
    const float* A   = (layer == 0) ? g_agg0 : g_agg1;
    float*       out = (layer == 0) ? g_h0   : g_h1;
    const int*  soff = (layer == 0) ? nullptr : g_off1;
    const int  nrows = (layer == 0) ? ND0 : ND1;

    int tid = threadIdx.x;
    int row0 = blockIdx.x * 32;

    float4* As4 = (float4*)As;
    for (int i = tid; i < 32 * 32; i += 256) {
        int r = i >> 5;
        int row = row0 + r;
        float4 v = make_float4(0.f, 0.f, 0.f, 0.f);
        if (row < nrows) {
            v = ((const float4*)A)[row * 32 + (i & 31)];
            if (soff) {
                float sc = rsqrtf(fmaxf((float)(soff[row + 1] - soff[row]), 1.f));
                v.x *= sc; v.y *= sc; v.z *= sc; v.w *= sc;
            }
        }
        As4[i] = v;
    }

    int cg = tid & 31;
    int rg = tid >> 5;
    float acc[4][4] = {};
    float4* Ws4 = (float4*)Ws;
    const float4* W4 = (const float4*)W;

    for (int kc = 0; kc < 128; kc += 32) {
        __syncthreads();
        for (int i = tid; i < 32 * 32; i += 256)
            Ws4[i] = W4[(kc + (i >> 5)) * 32 + (i & 31)];
        __syncthreads();
        #pragma unroll
        for (int k = 0; k < 32; k++) {
            float4 w = Ws4[k * 32 + cg];
            float a0 = As[(rg * 4 + 0) * 128 + kc + k];
            float a1 = As[(rg * 4 + 1) * 128 + kc + k];
            float a2 = As[(rg * 4 + 2) * 128 + kc + k];
            float a3 = As[(rg * 4 + 3) * 128 + kc + k];
            acc[0][0] += a0 * w.x; acc[0][1] += a0 * w.y; acc[0][2] += a0 * w.z; acc[0][3] += a0 * w.w;
            acc[1][0] += a1 * w.x; acc[1][1] += a1 * w.y; acc[1][2] += a1 * w.z; acc[1][3] += a1 * w.w;
            acc[2][0] += a2 * w.x; acc[2][1] += a2 * w.y; acc[2][2] += a2 * w.z; acc[2][3] += a2 * w.w;
            acc[3][0] += a3 * w.x; acc[3][1] += a3 * w.y; acc[3][2] += a3 * w.z; acc[3][3] += a3 * w.w;
        }
    }

    int c0 = cg * 4;
    float4 b4;
    b4.x = __ldg(&bias[c0 + 0]); b4.y = __ldg(&bias[c0 + 1]);
    b4.z = __ldg(&bias[c0 + 2]); b4.w = __ldg(&bias[c0 + 3]);
    #pragma unroll
    for (int r = 0; r < 4; r++) {
        int row = row0 + rg * 4 + r;
        if (row < nrows) {
            float4 o;
            o.x = fmaxf(acc[r][0] + b4.x, 0.f);
            o.y = fmaxf(acc[r][1] + b4.y, 0.f);
            o.z = fmaxf(acc[r][2] + b4.z, 0.f);
            o.w = fmaxf(acc[r][3] + b4.w, 0.f);
            ((float4*)out)[row * 32 + cg] = o;
        }
    }
}

// ---------------- output layer: [1024,128] @ [128,47] + b2 (in-deg scale, no relu) --
__global__ void mm_out_kernel(const float* __restrict__ W2, const float* __restrict__ b2,
                              float* __restrict__ out) {
    __shared__ float row[128];
    int r = blockIdx.x;
    int tid = threadIdx.x;  // 64
    float sc = rsqrtf(fmaxf((float)(g_off2[r + 1] - g_off2[r]), 1.f));
    float2 v = ((const float2*)g_agg2)[r * 64 + tid];
    ((float2*)row)[tid] = make_float2(v.x * sc, v.y * sc);
    __syncthreads();
    if (tid < NCLS) {
        float acc = 0.f;
        #pragma unroll 8
        for (int k = 0; k < 128; k++)
            acc += row[k] * __ldg(&W2[k * NCLS + tid]);
        out[r * NCLS + tid] = acc + __ldg(&b2[tid]);
    }
}

// ---------------- launch (only harness pointers + literals cross the boundary) ------
extern "C" void kernel_launch(void* const* d_in, const int* in_sizes, int n_in,
                              void* d_out, int out_size) {
    (void)in_sizes; (void)n_in; (void)out_size;
    const float* feats       = (const float*)d_in[0];
    const int*   src0        = (const int*)d_in[1];
    const int*   dst0        = (const int*)d_in[2];
    const int*   src1        = (const int*)d_in[3];
    const int*   dst1        = (const int*)d_in[4];
    const int*   src2        = (const int*)d_in[5];
    const int*   dst2        = (const int*)d_in[6];
    const int*   inverse_idx = (const int*)d_in[7];
    const int*   shuffle_idx = (const int*)d_in[8];
    const float* W0          = (const float*)d_in[9];
    const float* b0          = (const float*)d_in[10];
    const float* W1          = (const float*)d_in[11];
    const float* b1          = (const float*)d_in[12];
    const float* W2          = (const float*)d_in[13];
    const float* b2          = (const float*)d_in[14];
    float* out = (float*)d_out;

    zero_counts_kernel<<<(ND0 + 255) / 256, 256>>>();
    hist_all_kernel<<<(E0C + 255) / 256, 256>>>(src0, dst0, src1, dst1, src2, dst2);
    scan3_kernel<<<3, 512>>>();
    scatter_all_kernel<<<(E0C + 255) / 256, 256>>>(src0, dst0, src1, dst1, src2, dst2);

    // layer 0
    agg0_kernel<<<(ND0 * 32 + 255) / 256, 256>>>((const float4*)feats);
    mm128_kernel<<<(ND0 + 31) / 32, 256>>>(W0, b0, 0);

    // layer 1 (perm folded into gather)
    agg1_kernel<<<(ND1 * 32 + 255) / 256, 256>>>(inverse_idx, shuffle_idx);
    mm128_kernel<<<(ND1 + 31) / 32, 256>>>(W1, b1, 1);

    // layer 2
    agg2_kernel<<<(ND2 * 32 + 255) / 256, 256>>>();
    mm_out_kernel<<<ND2, 64>>>(W2, b2, out);
}

// round 11
// speedup vs baseline: 1.0492x; 1.0492x over previous
#include <cuda_runtime.h>
#include <cstdint>

#define ND0 100000
#define ND1 10000
#define ND2 1024
#define E0C 1000000
#define E1C 100000
#define E2C 10240
#define DH  128
#define NCLS 47

// ---------------- scratch (device globals; referenced ONLY from device code) --------
static __device__ int g_deg0[ND0];
static __device__ int g_indeg1[ND1];
static __device__ int g_outdeg1[ND0];
static __device__ int g_indeg2[ND2];
static __device__ int g_outdeg2[ND1];
static __device__ int g_off0[ND0 + 1];
static __device__ int g_off1[ND1 + 1];
static __device__ int g_off2[ND2 + 1];
static __device__ int g_csr0[E0C];
static __device__ int g_csr1[E1C];
static __device__ int g_csr2[E2C];
static __device__ float g_agg0[ND0 * DH];
static __device__ float g_h0[ND0 * DH];
static __device__ float g_agg1[ND1 * DH];
static __device__ float g_h1[ND1 * DH];
static __device__ float g_agg2[ND2 * DH];
static __device__ float g_w0t[DH * DH];   // W0 transposed: [n][k]
static __device__ float g_w1t[DH * DH];   // W1 transposed: [n][k]

// ---------------- counters zero ----------------
__global__ void zero_counts_kernel() {
    int i = blockIdx.x * blockDim.x + threadIdx.x;
    if (i < ND0) g_deg0[i] = 0;
    if (i < ND1) g_indeg1[i] = 0;
    if (i < ND0) g_outdeg1[i] = 0;
    if (i < ND2) g_indeg2[i] = 0;
    if (i < ND1) g_outdeg2[i] = 0;
}

// ---------------- W transpose (once, tiny) ----------------
__global__ void transpose_w_kernel(const float* __restrict__ W0, const float* __restrict__ W1) {
    int i = blockIdx.x * blockDim.x + threadIdx.x;
    if (i < DH * DH) {
        int n = i >> 7, k = i & 127;
        g_w0t[i] = W0[k * DH + n];
        g_w1t[i] = W1[k * DH + n];
    }
}

// ---------------- histograms ----------------
__global__ void hist_all_kernel(const int* __restrict__ src0, const int* __restrict__ dst0,
                                const int* __restrict__ src1, const int* __restrict__ dst1,
                                const int* __restrict__ src2, const int* __restrict__ dst2) {
    int i = blockIdx.x * blockDim.x + threadIdx.x;
    if (i < E0C) atomicAdd(&g_deg0[dst0[i]], 1);
    if (i < E1C) { atomicAdd(&g_indeg1[dst1[i]], 1); atomicAdd(&g_outdeg1[src1[i]], 1); }
    if (i < E2C) { atomicAdd(&g_indeg2[dst2[i]], 1); atomicAdd(&g_outdeg2[src2[i]], 1); }
}

// ---------------- single-block exclusive scan ----------------
__device__ void exscan_block(const int* __restrict__ deg, int* __restrict__ off, int n) {
    __shared__ int warp_sums[16];
    __shared__ int s_carry;
    const int T = 512;
    int tid = threadIdx.x, lane = tid & 31, w = tid >> 5;
    if (tid == 0) s_carry = 0;
    __syncthreads();
    for (int base = 0; base < n; base += T * 4) {
        int idx = base + tid * 4;
        int4 v = make_int4(0, 0, 0, 0);
        if (idx + 3 < n) v = *(const int4*)(deg + idx);
        else {
            if (idx     < n) v.x = deg[idx];
            if (idx + 1 < n) v.y = deg[idx + 1];
            if (idx + 2 < n) v.z = deg[idx + 2];
            if (idx + 3 < n) v.w = deg[idx + 3];
        }
        int s1 = v.x, s2 = s1 + v.y, s3 = s2 + v.z, s4 = s3 + v.w;
        int x = s4;
        #pragma unroll
        for (int d = 1; d < 32; d <<= 1) {
            int y = __shfl_up_sync(0xffffffffu, x, d);
            if (lane >= d) x += y;
        }
        if (lane == 31) warp_sums[w] = x;
        __syncthreads();
        if (w == 0 && lane < 16) {
            int s = warp_sums[lane];
            #pragma unroll
            for (int d = 1; d < 16; d <<= 1) {
                int y = __shfl_up_sync(0x0000ffffu, s, d);
                if (lane >= d) s += y;
            }
            warp_sums[lane] = s;
        }
        __syncthreads();
        int pre = s_carry + (w > 0 ? warp_sums[w - 1] : 0) + (x - s4);
        if (idx     < n) off[idx]     = pre;
        if (idx + 1 < n) off[idx + 1] = pre + s1;
        if (idx + 2 < n) off[idx + 2] = pre + s2;
        if (idx + 3 < n) off[idx + 3] = pre + s3;
        __syncthreads();
        if (tid == 0) s_carry += warp_sums[15];
        __syncthreads();
    }
    if (tid == 0) off[n] = s_carry;
}

__global__ void scan3_kernel() {
    if (blockIdx.x == 0)      exscan_block(g_deg0,   g_off0, ND0);
    else if (blockIdx.x == 1) exscan_block(g_indeg1, g_off1, ND1);
    else                      exscan_block(g_indeg2, g_off2, ND2);
}

// ---------------- CSR scatter ----------------
__global__ void scatter_all_kernel(const int* __restrict__ src0, const int* __restrict__ dst0,
                                   const int* __restrict__ src1, const int* __restrict__ dst1,
                                   const int* __restrict__ src2, const int* __restrict__ dst2) {
    int i = blockIdx.x * blockDim.x + threadIdx.x;
    if (i < E0C) {
        int d = dst0[i];
        int old = atomicSub(&g_deg0[d], 1);
        g_csr0[g_off0[d] + old - 1] = src0[i];
    }
    if (i < E1C) {
        int d = dst1[i];
        int old = atomicSub(&g_indeg1[d], 1);
        g_csr1[g_off1[d] + old - 1] = src1[i];
    }
    if (i < E2C) {
        int d = dst2[i];
        int old = atomicSub(&g_indeg2[d], 1);
        g_csr2[g_off2[d] + old - 1] = src2[i];
    }
}

// ---------------- layer 0 aggregation: warp per node, 2-edge unroll for MLP --------
__global__ void agg0_kernel(const float4* __restrict__ feats4) {
    int gid = blockIdx.x * blockDim.x + threadIdx.x;
    int node = gid >> 5;
    int lane = gid & 31;
    if (node >= ND0) return;
    int s = g_off0[node], e = g_off0[node + 1];
    float4 a0 = make_float4(0.f, 0.f, 0.f, 0.f);
    float4 a1 = make_float4(0.f, 0.f, 0.f, 0.f);
    int i = s;
    for (; i + 1 < e; i += 2) {
        int u0 = g_csr0[i], u1 = g_csr0[i + 1];
        float4 v0 = __ldg(&feats4[u0 * 32 + lane]);
        float4 v1 = __ldg(&feats4[u1 * 32 + lane]);
        a0.x += v0.x; a0.y += v0.y; a0.z += v0.z; a0.w += v0.w;
        a1.x += v1.x; a1.y += v1.y; a1.z += v1.z; a1.w += v1.w;
    }
    if (i < e) {
        int u = g_csr0[i];
        float4 v = __ldg(&feats4[u * 32 + lane]);
        a0.x += v.x; a0.y += v.y; a0.z += v.z; a0.w += v.w;
    }
    a0.x += a1.x; a0.y += a1.y; a0.z += a1.z; a0.w += a1.w;
    ((float4*)g_agg0)[node * 32 + lane] = a0;
}

// ---------------- layer 1 aggregation: perm-folded gather + out-degree scale --------
__global__ void agg1_kernel(const int* __restrict__ inverse_idx,
                            const int* __restrict__ shuffle_idx) {
    int gid = blockIdx.x * blockDim.x + threadIdx.x;
    int node = gid >> 5;
    int lane = gid & 31;
    if (node >= ND1) return;
    int s = g_off1[node], e = g_off1[node + 1];
    float4 acc = make_float4(0.f, 0.f, 0.f, 0.f);
    for (int i = s; i < e; i++) {
        int u = g_csr1[i];
        int row = inverse_idx[shuffle_idx[u]];
        float sc = rsqrtf(fmaxf((float)g_outdeg1[u], 1.f));
        float4 v = ((const float4*)g_h0)[row * 32 + lane];
        acc.x += v.x * sc; acc.y += v.y * sc; acc.z += v.z * sc; acc.w += v.w * sc;
    }
    ((float4*)g_agg1)[node * 32 + lane] = acc;
}

// ---------------- layer 2 aggregation ----------------
__global__ void agg2_kernel() {
    int gid = blockIdx.x * blockDim.x + threadIdx.x;
    int node = gid >> 5;
    int lane = gid & 31;
    if (node >= ND2) return;
    int s = g_off2[node], e = g_off2[node + 1];
    float4 acc = make_float4(0.f, 0.f, 0.f, 0.f);
    for (int i = s; i < e; i++) {
        int u = g_csr2[i];
        float sc = rsqrtf(fmaxf((float)g_outdeg2[u], 1.f));
        float4 v = ((const float4*)g_h1)[u * 32 + lane];
        acc.x += v.x * sc; acc.y += v.y * sc; acc.z += v.z * sc; acc.w += v.w * sc;
    }
    ((float4*)g_agg2)[node * 32 + lane] = acc;
}

// ---------------- tf32 mma.sync GEMM: [128-row tile] x [128,128] -------------------
// D = A @ Wt^T, Wt[n][k]. Epilogue: out = relu(sc(row)*D + bias); sc only for layer 1.
// smem: A 128x132 + W 128x132 fp32 (132-float stride => conflict-free fragment LDS).
#define MMPAD 132
__device__ __forceinline__ uint32_t f2tf32(float f) {
    uint32_t u;
    asm("cvt.rna.tf32.f32 %0, %1;" : "=r"(u) : "f"(f));
    return u;
}
__global__ void __launch_bounds__(256, 1) mm_tf32_kernel(const float* __restrict__ bias,
                                                         int layer) {
    extern __shared__ float sm[];
    float* As = sm;                    // 128 x 132
    float* Ws = sm + 128 * MMPAD;      // 128 x 132

    const float* A    = layer ? g_agg1 : g_agg0;
    float*       outp = layer ? g_h1   : g_h0;
    const float* Wt   = layer ? g_w1t  : g_w0t;
    const int   nrows = layer ? ND1 : ND0;

    int tid = threadIdx.x, wid = tid >> 5, lane = tid & 31;
    int row0 = blockIdx.x * 128;

    // stage A (zero-padded tail) and Wt
    for (int i = tid; i < 4096; i += 256) {
        int r = i >> 5, c4 = i & 31;
        float4 va = make_float4(0.f, 0.f, 0.f, 0.f);
        int row = row0 + r;
        if (row < nrows) va = ((const float4*)A)[row * 32 + c4];
        *(float4*)(As + r * MMPAD + c4 * 4) = va;
        *(float4*)(Ws + r * MMPAD + c4 * 4) = ((const float4*)Wt)[i];
    }
    __syncthreads();

    // each warp: 16 rows (wid*16) x 128 cols = 16 m16n8 tiles
    int rw = wid * 16;
    int q = lane >> 2, m4 = lane & 3;      // groupID, threadID_in_group
    float d[16][4];
    #pragma unroll
    for (int t = 0; t < 16; t++) { d[t][0] = d[t][1] = d[t][2] = d[t][3] = 0.f; }

    for (int k = 0; k < 16; k++) {
        int kc = k * 8 + m4;
        uint32_t a0 = f2tf32(As[(rw + q) * MMPAD + kc]);
        uint32_t a1 = f2tf32(As[(rw + q + 8) * MMPAD + kc]);
        uint32_t a2 = f2tf32(As[(rw + q) * MMPAD + kc + 4]);
        uint32_t a3 = f2tf32(As[(rw + q + 8) * MMPAD + kc + 4]);
        #pragma unroll
        for (int t = 0; t < 16; t++) {
            uint32_t b0 = f2tf32(Ws[(t * 8 + q) * MMPAD + kc]);
            uint32_t b1 = f2tf32(Ws[(t * 8 + q) * MMPAD + kc + 4]);
            asm volatile(
                "mma.sync.aligned.m16n8k8.row.col.f32.tf32.tf32.f32 "
                "{%0,%1,%2,%3}, {%4,%5,%6,%7}, {%8,%9}, {%0,%1,%2,%3};"
                : "+f"(d[t][0]), "+f"(d[t][1]), "+f"(d[t][2]), "+f"(d[t][3])
                : "r"(a0), "r"(a1), "r"(a2), "r"(a3), "r"(b0), "r"(b1));
        }
    }

    // epilogue: rows rA = row0+rw+q, rB = rA+8; cols t*8 + m4*2 (+1)
    int rA = row0 + rw + q;
    int rB = rA + 8;
    float scA = 1.f, scB = 1.f;
    if (layer == 1) {
        if (rA < nrows) scA = rsqrtf(fmaxf((float)(g_off1[rA + 1] - g_off1[rA]), 1.f));
        if (rB < nrows) scB = rsqrtf(fmaxf((float)(g_off1[rB + 1] - g_off1[rB]), 1.f));
    }
    #pragma unroll
    for (int t = 0; t < 16; t++) {
        int c = t * 8 + m4 * 2;
        float bx = __ldg(&bias[c]), by = __ldg(&bias[c + 1]);
        if (rA < nrows) {
            float2 o;
            o.x = fmaxf(d[t][0] * scA + bx, 0.f);
            o.y = fmaxf(d[t][1] * scA + by, 0.f);
            *(float2*)(outp + rA * DH + c) = o;
        }
        if (rB < nrows) {
            float2 o;
            o.x = fmaxf(d[t][2] * scB + bx, 0.f);
            o.y = fmaxf(d[t][3] * scB + by, 0.f);
            *(float2*)(outp + rB * DH + c) = o;
        }
    }
}

// ---------------- output layer: [1024,128] @ [128,47] + b2 (in-deg scale) ----------
__global__ void mm_out_kernel(const float* __restrict__ W2, const float* __restrict__ b2,
                              float* __restrict__ out) {
    __shared__ float row[128];
    int r = blockIdx.x;
    int tid = threadIdx.x;  // 64
    float sc = rsqrtf(fmaxf((float)(g_off2[r + 1] - g_off2[r]), 1.f));
    float2 v = ((const float2*)g_agg2)[r * 64 + tid];
    ((float2*)row)[tid] = make_float2(v.x * sc, v.y * sc);
    __syncthreads();
    if (tid < NCLS) {
        float acc = 0.f;
        #pragma unroll 8
        for (int k = 0; k < 128; k++)
            acc += row[k] * __ldg(&W2[k * NCLS + tid]);
        out[r * NCLS + tid] = acc + __ldg(&b2[tid]);
    }
}

// ---------------- launch ----------------
extern "C" void kernel_launch(void* const* d_in, const int* in_sizes, int n_in,
                              void* d_out, int out_size) {
    (void)in_sizes; (void)n_in; (void)out_size;
    const float* feats       = (const float*)d_in[0];
    const int*   src0        = (const int*)d_in[1];
    const int*   dst0        = (const int*)d_in[2];
    const int*   src1        = (const int*)d_in[3];
    const int*   dst1        = (const int*)d_in[4];
    const int*   src2        = (const int*)d_in[5];
    const int*   dst2        = (const int*)d_in[6];
    const int*   inverse_idx = (const int*)d_in[7];
    const int*   shuffle_idx = (const int*)d_in[8];
    const float* W0          = (const float*)d_in[9];
    const float* b0          = (const float*)d_in[10];
    const float* W1          = (const float*)d_in[11];
    const float* b1          = (const float*)d_in[12];
    const float* W2          = (const float*)d_in[13];
    const float* b2          = (const float*)d_in[14];
    float* out = (float*)d_out;

    const int MM_SMEM = 2 * 128 * MMPAD * 4;  // 135168 bytes
    cudaFuncSetAttribute(mm_tf32_kernel,
                         cudaFuncAttributeMaxDynamicSharedMemorySize, MM_SMEM);

    zero_counts_kernel<<<(ND0 + 255) / 256, 256>>>();
    transpose_w_kernel<<<(DH * DH + 255) / 256, 256>>>(W0, W1);
    hist_all_kernel<<<(E0C + 255) / 256, 256>>>(src0, dst0, src1, dst1, src2, dst2);
    scan3_kernel<<<3, 512>>>();
    scatter_all_kernel<<<(E0C + 255) / 256, 256>>>(src0, dst0, src1, dst1, src2, dst2);

    // layer 0
    agg0_kernel<<<(ND0 * 32 + 255) / 256, 256>>>((const float4*)feats);
    mm_tf32_kernel<<<(ND0 + 127) / 128, 256, MM_SMEM>>>(b0, 0);

    // layer 1 (perm folded into gather)
    agg1_kernel<<<(ND1 * 32 + 255) / 256, 256>>>(inverse_idx, shuffle_idx);
    mm_tf32_kernel<<<(ND1 + 127) / 128, 256, MM_SMEM>>>(b1, 1);

    // layer 2
    agg2_kernel<<<(ND2 * 32 + 255) / 256, 256>>>();
    mm_out_kernel<<<ND2, 64>>>(W2, b2, out);
}

// round 14
// speedup vs baseline: 1.2499x; 1.1913x over previous
#include <cuda_runtime.h>
#include <cstdint>

#define ND0 100000
#define ND1 10000
#define ND2 1024
#define E0C 1000000
#define E1C 100000
#define E2C 10240
#define DH  128
#define NCLS 47

// scan partitioning: 2048 elements per block (512 thr x 4)
#define SCHUNK 2048
#define NB0 ((ND0 + SCHUNK - 1) / SCHUNK)   // 49
#define NB1 ((ND1 + SCHUNK - 1) / SCHUNK)   // 5
#define NB2 ((ND2 + SCHUNK - 1) / SCHUNK)   // 1
#define NBT (NB0 + NB1 + NB2)               // 55

// ---------------- scratch (device globals; referenced ONLY from device code) --------
static __device__ int g_deg0[ND0];
static __device__ int g_indeg1[ND1];
static __device__ int g_outdeg1[ND0];
static __device__ int g_indeg2[ND2];
static __device__ int g_outdeg2[ND1];
static __device__ int g_off0[ND0 + 1];
static __device__ int g_off1[ND1 + 1];
static __device__ int g_off2[ND2 + 1];
static __device__ int g_bsum0[NB0];
static __device__ int g_bsum1[NB1];
static __device__ int g_bsum2[NB2];
static __device__ int g_csr0[E0C];
static __device__ int g_csr1[E1C];
static __device__ int g_csr2[E2C];
static __device__ float g_agg0[ND0 * DH];
static __device__ float g_h0[ND0 * DH];
static __device__ float g_agg1[ND1 * DH];
static __device__ float g_h1[ND1 * DH];
static __device__ float g_agg2[ND2 * DH];
static __device__ float g_w0t[DH * DH];   // W0 transposed: [n][k]
static __device__ float g_w1t[DH * DH];   // W1 transposed: [n][k]

// ---------------- init: zero counters + transpose W (fused) ----------------
__global__ void init_kernel(const float* __restrict__ W0, const float* __restrict__ W1) {
    int i = blockIdx.x * blockDim.x + threadIdx.x;
    if (i < ND0) { g_deg0[i] = 0; g_outdeg1[i] = 0; }
    if (i < ND1) { g_indeg1[i] = 0; g_outdeg2[i] = 0; }
    if (i < ND2) g_indeg2[i] = 0;
    if (i < DH * DH) {
        int n = i >> 7, k = i & 127;
        g_w0t[i] = W0[k * DH + n];
        g_w1t[i] = W1[k * DH + n];
    }
}

// ---------------- histograms ----------------
__global__ void hist_all_kernel(const int* __restrict__ src0, const int* __restrict__ dst0,
                                const int* __restrict__ src1, const int* __restrict__ dst1,
                                const int* __restrict__ src2, const int* __restrict__ dst2) {
    int i = blockIdx.x * blockDim.x + threadIdx.x;
    if (i < E0C) atomicAdd(&g_deg0[dst0[i]], 1);
    if (i < E1C) { atomicAdd(&g_indeg1[dst1[i]], 1); atomicAdd(&g_outdeg1[src1[i]], 1); }
    if (i < E2C) { atomicAdd(&g_indeg2[dst2[i]], 1); atomicAdd(&g_outdeg2[src2[i]], 1); }
}

// ---------------- multi-block scan: phase mapping ----------------
__device__ __forceinline__ void scan_map(int b, const int*& deg, int*& off, int*& bsum,
                                         int& n, int& cb) {
    if (b < NB0)            { deg = g_deg0;   off = g_off0; bsum = g_bsum0; n = ND0; cb = b; }
    else if (b < NB0 + NB1) { deg = g_indeg1; off = g_off1; bsum = g_bsum1; n = ND1; cb = b - NB0; }
    else                    { deg = g_indeg2; off = g_off2; bsum = g_bsum2; n = ND2; cb = b - NB0 - NB1; }
}

// P1: per-block exclusive scan of one 2048-chunk; chunk total -> bsum[cb]
__global__ void scan_p1_kernel() {
    __shared__ int warp_sums[16];
    const int* deg; int* off; int* bsum; int n, cb;
    scan_map(blockIdx.x, deg, off, bsum, n, cb);
    int tid = threadIdx.x, lane = tid & 31, w = tid >> 5;
    int idx = cb * SCHUNK + tid * 4;

    int4 v = make_int4(0, 0, 0, 0);
    if (idx + 3 < n) v = *(const int4*)(deg + idx);
    else {
        if (idx     < n) v.x = deg[idx];
        if (idx + 1 < n) v.y = deg[idx + 1];
        if (idx + 2 < n) v.z = deg[idx + 2];
        if (idx + 3 < n) v.w = deg[idx + 3];
    }
    int s1 = v.x, s2 = s1 + v.y, s3 = s2 + v.z, s4 = s3 + v.w;
    int x = s4;
    #pragma unroll
    for (int d = 1; d < 32; d <<= 1) {
        int y = __shfl_up_sync(0xffffffffu, x, d);
        if (lane >= d) x += y;
    }
    if (lane == 31) warp_sums[w] = x;
    __syncthreads();
    if (w == 0 && lane < 16) {
        int s = warp_sums[lane];
        #pragma unroll
        for (int d = 1; d < 16; d <<= 1) {
            int y = __shfl_up_sync(0x0000ffffu, s, d);
            if (lane >= d) s += y;
        }
        warp_sums[lane] = s;
    }
    __syncthreads();
    int pre = (w > 0 ? warp_sums[w - 1] : 0) + (x - s4);
    if (idx     < n) off[idx]     = pre;
    if (idx + 1 < n) off[idx + 1] = pre + s1;
    if (idx + 2 < n) off[idx + 2] = pre + s2;
    if (idx + 3 < n) off[idx + 3] = pre + s3;
    if (tid == 0) bsum[cb] = warp_sums[15];
}

// P2: one warp per array scans its <=64 block sums; writes exclusive bases + off[n]
__global__ void scan_p2_kernel() {
    int w = threadIdx.x >> 5, lane = threadIdx.x & 31;
    int* bsum; int cnt; int* offn;
    if (w == 0)      { bsum = g_bsum0; cnt = NB0; offn = &g_off0[ND0]; }
    else if (w == 1) { bsum = g_bsum1; cnt = NB1; offn = &g_off1[ND1]; }
    else             { bsum = g_bsum2; cnt = NB2; offn = &g_off2[ND2]; }
    int v0 = (lane < cnt) ? bsum[lane] : 0;
    int v1 = (lane + 32 < cnt) ? bsum[lane + 32] : 0;
    int s0 = v0, s1v = v1;
    #pragma unroll
    for (int d = 1; d < 32; d <<= 1) {
        int y0 = __shfl_up_sync(0xffffffffu, s0, d);
        int y1 = __shfl_up_sync(0xffffffffu, s1v, d);
        if (lane >= d) { s0 += y0; s1v += y1; }
    }
    int tot0 = __shfl_sync(0xffffffffu, s0, 31);
    s1v += tot0;
    int tot = __shfl_sync(0xffffffffu, s1v, 31);
    if (lane < cnt) bsum[lane] = s0 - v0;
    if (lane + 32 < cnt) bsum[lane + 32] = s1v - v1;
    if (lane == 0) *offn = tot;
}

// P3: add block base to each chunk element
__global__ void scan_p3_kernel() {
    const int* deg; int* off; int* bsum; int n, cb;
    scan_map(blockIdx.x, deg, off, bsum, n, cb);
    int add = bsum[cb];
    if (add == 0) return;
    int idx = cb * SCHUNK + threadIdx.x * 4;
    if (idx + 3 < n) {
        int4 t = *(int4*)(off + idx);
        t.x += add; t.y += add; t.z += add; t.w += add;
        *(int4*)(off + idx) = t;
    } else {
        if (idx     < n) off[idx]     += add;
        if (idx + 1 < n) off[idx + 1] += add;
        if (idx + 2 < n) off[idx + 2] += add;
        if (idx + 3 < n) off[idx + 3] += add;
    }
}

// ---------------- CSR scatter ----------------
__global__ void scatter_all_kernel(const int* __restrict__ src0, const int* __restrict__ dst0,
                                   const int* __restrict__ src1, const int* __restrict__ dst1,
                                   const int* __restrict__ src2, const int* __restrict__ dst2) {
    int i = blockIdx.x * blockDim.x + threadIdx.x;
    if (i < E0C) {
        int d = dst0[i];
        int old = atomicSub(&g_deg0[d], 1);
        g_csr0[g_off0[d] + old - 1] = src0[i];
    }
    if (i < E1C) {
        int d = dst1[i];
        int old = atomicSub(&g_indeg1[d], 1);
        g_csr1[g_off1[d] + old - 1] = src1[i];
    }
    if (i < E2C) {
        int d = dst2[i];
        int old = atomicSub(&g_indeg2[d], 1);
        g_csr2[g_off2[d] + old - 1] = src2[i];
    }
}

// ---------------- layer 0 aggregation: warp per node, 2-edge unroll for MLP --------
__global__ void agg0_kernel(const float4* __restrict__ feats4) {
    int gid = blockIdx.x * blockDim.x + threadIdx.x;
    int node = gid >> 5;
    int lane = gid & 31;
    if (node >= ND0) return;
    int s = g_off0[node], e = g_off0[node + 1];
    float4 a0 = make_float4(0.f, 0.f, 0.f, 0.f);
    float4 a1 = make_float4(0.f, 0.f, 0.f, 0.f);
    int i = s;
    for (; i + 1 < e; i += 2) {
        int u0 = g_csr0[i], u1 = g_csr0[i + 1];
        float4 v0 = __ldg(&feats4[u0 * 32 + lane]);
        float4 v1 = __ldg(&feats4[u1 * 32 + lane]);
        a0.x += v0.x; a0.y += v0.y; a0.z += v0.z; a0.w += v0.w;
        a1.x += v1.x; a1.y += v1.y; a1.z += v1.z; a1.w += v1.w;
    }
    if (i < e) {
        int u = g_csr0[i];
        float4 v = __ldg(&feats4[u * 32 + lane]);
        a0.x += v.x; a0.y += v.y; a0.z += v.z; a0.w += v.w;
    }
    a0.x += a1.x; a0.y += a1.y; a0.z += a1.z; a0.w += a1.w;
    ((float4*)g_agg0)[node * 32 + lane] = a0;
}

// ---------------- layer 1 aggregation: perm-folded gather + out-degree scale --------
__global__ void agg1_kernel(const int* __restrict__ inverse_idx,
                            const int* __restrict__ shuffle_idx) {
    int gid = blockIdx.x * blockDim.x + threadIdx.x;
    int node = gid >> 5;
    int lane = gid & 31;
    if (node >= ND1) return;
    int s = g_off1[node], e = g_off1[node + 1];
    float4 acc = make_float4(0.f, 0.f, 0.f, 0.f);
    for (int i = s; i < e; i++) {
        int u = g_csr1[i];
        int row = inverse_idx[shuffle_idx[u]];
        float sc = rsqrtf(fmaxf((float)g_outdeg1[u], 1.f));
        float4 v = ((const float4*)g_h0)[row * 32 + lane];
        acc.x += v.x * sc; acc.y += v.y * sc; acc.z += v.z * sc; acc.w += v.w * sc;
    }
    ((float4*)g_agg1)[node * 32 + lane] = acc;
}

// ---------------- layer 2 aggregation ----------------
__global__ void agg2_kernel() {
    int gid = blockIdx.x * blockDim.x + threadIdx.x;
    int node = gid >> 5;
    int lane = gid & 31;
    if (node >= ND2) return;
    int s = g_off2[node], e = g_off2[node + 1];
    float4 acc = make_float4(0.f, 0.f, 0.f, 0.f);
    for (int i = s; i < e; i++) {
        int u = g_csr2[i];
        float sc = rsqrtf(fmaxf((float)g_outdeg2[u], 1.f));
        float4 v = ((const float4*)g_h1)[u * 32 + lane];
        acc.x += v.x * sc; acc.y += v.y * sc; acc.z += v.z * sc; acc.w += v.w * sc;
    }
    ((float4*)g_agg2)[node * 32 + lane] = acc;
}

// ---------------- tf32 mma.sync GEMM: [128-row tile] x [128,128] -------------------
// D = A @ Wt^T, Wt[n][k]. Epilogue: out = relu(sc(row)*D + bias); sc only for layer 1.
#define MMPAD 132
__device__ __forceinline__ uint32_t f2tf32(float f) {
    uint32_t u;
    asm("cvt.rna.tf32.f32 %0, %1;" : "=r"(u) : "f"(f));
    return u;
}
__global__ void __launch_bounds__(256, 1) mm_tf32_kernel(const float* __restrict__ bias,
                                                         int layer) {
    extern __shared__ float sm[];
    float* As = sm;                    // 128 x 132
    float* Ws = sm + 128 * MMPAD;      // 128 x 132

    const float* A    = layer ? g_agg1 : g_agg0;
    float*       outp = layer ? g_h1   : g_h0;
    const float* Wt   = layer ? g_w1t  : g_w0t;
    const int   nrows = layer ? ND1 : ND0;

    int tid = threadIdx.x, wid = tid >> 5, lane = tid & 31;
    int row0 = blockIdx.x * 128;

    for (int i = tid; i < 4096; i += 256) {
        int r = i >> 5, c4 = i & 31;
        float4 va = make_float4(0.f, 0.f, 0.f, 0.f);
        int row = row0 + r;
        if (row < nrows) va = ((const float4*)A)[row * 32 + c4];
        *(float4*)(As + r * MMPAD + c4 * 4) = va;
        *(float4*)(Ws + r * MMPAD + c4 * 4) = ((const float4*)Wt)[i];
    }
    __syncthreads();

    int rw = wid * 16;
    int q = lane >> 2, m4 = lane & 3;
    float d[16][4];
    #pragma unroll
    for (int t = 0; t < 16; t++) { d[t][0] = d[t][1] = d[t][2] = d[t][3] = 0.f; }

    for (int k = 0; k < 16; k++) {
        int kc = k * 8 + m4;
        uint32_t a0 = f2tf32(As[(rw + q) * MMPAD + kc]);
        uint32_t a1 = f2tf32(As[(rw + q + 8) * MMPAD + kc]);
        uint32_t a2 = f2tf32(As[(rw + q) * MMPAD + kc + 4]);
        uint32_t a3 = f2tf32(As[(rw + q + 8) * MMPAD + kc + 4]);
        #pragma unroll
        for (int t = 0; t < 16; t++) {
            uint32_t b0 = f2tf32(Ws[(t * 8 + q) * MMPAD + kc]);
            uint32_t b1 = f2tf32(Ws[(t * 8 + q) * MMPAD + kc + 4]);
            asm volatile(
                "mma.sync.aligned.m16n8k8.row.col.f32.tf32.tf32.f32 "
                "{%0,%1,%2,%3}, {%4,%5,%6,%7}, {%8,%9}, {%0,%1,%2,%3};"
                : "+f"(d[t][0]), "+f"(d[t][1]), "+f"(d[t][2]), "+f"(d[t][3])
                : "r"(a0), "r"(a1), "r"(a2), "r"(a3), "r"(b0), "r"(b1));
        }
    }

    int rA = row0 + rw + q;
    int rB = rA + 8;
    float scA = 1.f, scB = 1.f;
    if (layer == 1) {
        if (rA < nrows) scA = rsqrtf(fmaxf((float)(g_off1[rA + 1] - g_off1[rA]), 1.f));
        if (rB < nrows) scB = rsqrtf(fmaxf((float)(g_off1[rB + 1] - g_off1[rB]), 1.f));
    }
    #pragma unroll
    for (int t = 0; t < 16; t++) {
        int c = t * 8 + m4 * 2;
        float bx = __ldg(&bias[c]), by = __ldg(&bias[c + 1]);
        if (rA < nrows) {
            float2 o;
            o.x = fmaxf(d[t][0] * scA + bx, 0.f);
            o.y = fmaxf(d[t][1] * scA + by, 0.f);
            *(float2*)(outp + rA * DH + c) = o;
        }
        if (rB < nrows) {
            float2 o;
            o.x = fmaxf(d[t][2] * scB + bx, 0.f);
            o.y = fmaxf(d[t][3] * scB + by, 0.f);
            *(float2*)(outp + rB * DH + c) = o;
        }
    }
}

// ---------------- output layer: [1024,128] @ [128,47] + b2 (in-deg scale) ----------
__global__ void mm_out_kernel(const float* __restrict__ W2, const float* __restrict__ b2,
                              float* __restrict__ out) {
    __shared__ float row[128];
    int r = blockIdx.x;
    int tid = threadIdx.x;  // 64
    float sc = rsqrtf(fmaxf((float)(g_off2[r + 1] - g_off2[r]), 1.f));
    float2 v = ((const float2*)g_agg2)[r * 64 + tid];
    ((float2*)row)[tid] = make_float2(v.x * sc, v.y * sc);
    __syncthreads();
    if (tid < NCLS) {
        float acc = 0.f;
        #pragma unroll 8
        for (int k = 0; k < 128; k++)
            acc += row[k] * __ldg(&W2[k * NCLS + tid]);
        out[r * NCLS + tid] = acc + __ldg(&b2[tid]);
    }
}

// ---------------- launch ----------------
extern "C" void kernel_launch(void* const* d_in, const int* in_sizes, int n_in,
                              void* d_out, int out_size) {
    (void)in_sizes; (void)n_in; (void)out_size;
    const float* feats       = (const float*)d_in[0];
    const int*   src0        = (const int*)d_in[1];
    const int*   dst0        = (const int*)d_in[2];
    const int*   src1        = (const int*)d_in[3];
    const int*   dst1        = (const int*)d_in[4];
    const int*   src2        = (const int*)d_in[5];
    const int*   dst2        = (const int*)d_in[6];
    const int*   inverse_idx = (const int*)d_in[7];
    const int*   shuffle_idx = (const int*)d_in[8];
    const float* W0          = (const float*)d_in[9];
    const float* b0          = (const float*)d_in[10];
    const float* W1          = (const float*)d_in[11];
    const float* b1          = (const float*)d_in[12];
    const float* W2          = (const float*)d_in[13];
    const float* b2          = (const float*)d_in[14];
    float* out = (float*)d_out;

    const int MM_SMEM = 2 * 128 * MMPAD * 4;  // 135168 bytes
    cudaFuncSetAttribute(mm_tf32_kernel,
                         cudaFuncAttributeMaxDynamicSharedMemorySize, MM_SMEM);

    init_kernel<<<(ND0 + 255) / 256, 256>>>(W0, W1);
    hist_all_kernel<<<(E0C + 255) / 256, 256>>>(src0, dst0, src1, dst1, src2, dst2);
    scan_p1_kernel<<<NBT, 512>>>();
    scan_p2_kernel<<<1, 96>>>();
    scan_p3_kernel<<<NBT, 512>>>();
    scatter_all_kernel<<<(E0C + 255) / 256, 256>>>(src0, dst0, src1, dst1, src2, dst2);

    // layer 0
    agg0_kernel<<<(ND0 * 32 + 255) / 256, 256>>>((const float4*)feats);
    mm_tf32_kernel<<<(ND0 + 127) / 128, 256, MM_SMEM>>>(b0, 0);

    // layer 1 (perm folded into gather)
    agg1_kernel<<<(ND1 * 32 + 255) / 256, 256>>>(inverse_idx, shuffle_idx);
    mm_tf32_kernel<<<(ND1 + 127) / 128, 256, MM_SMEM>>>(b1, 1);

    // layer 2
    agg2_kernel<<<(ND2 * 32 + 255) / 256, 256>>>();
    mm_out_kernel<<<ND2, 64>>>(W2, b2, out);
}

// round 15
// speedup vs baseline: 1.7664x; 1.4132x over previous
#include <cuda_runtime.h>
#include <cstdint>

#define ND0 100000
#define ND1 10000
#define ND2 1024
#define E0C 1000000
#define E1C 100000
#define E2C 10240
#define DH  128
#define NCLS 47

// scan partitioning: 2048 elements per block (512 thr x 4)
#define SCHUNK 2048
#define NB0 ((ND0 + SCHUNK - 1) / SCHUNK)   // 49
#define NB1 ((ND1 + SCHUNK - 1) / SCHUNK)   // 5
#define NB2 ((ND2 + SCHUNK - 1) / SCHUNK)   // 1
#define NBT (NB0 + NB1 + NB2)               // 55

// ---------------- scratch (device globals; referenced ONLY from device code) --------
static __device__ int g_deg0[ND0];
static __device__ int g_indeg1[ND1];
static __device__ int g_outdeg1[ND0];
static __device__ int g_indeg2[ND2];
static __device__ int g_outdeg2[ND1];
static __device__ int g_off0[ND0 + 1];
static __device__ int g_off1[ND1 + 1];
static __device__ int g_off2[ND2 + 1];
static __device__ int g_bsum0[NB0];
static __device__ int g_bsum1[NB1];
static __device__ int g_bsum2[NB2];
static __device__ int g_csr0[E0C];
static __device__ int g_csr1[E1C];
static __device__ int g_csr2[E2C];
static __device__ float g_agg0[ND0 * DH];
static __device__ float g_h0[ND0 * DH];
static __device__ float g_agg1[ND1 * DH];
static __device__ float g_h1[ND1 * DH];
static __device__ float g_w0t[DH * DH];   // W0^T as tf32 BIT PATTERNS, [n][k]
static __device__ float g_w1t[DH * DH];   // W1^T as tf32 BIT PATTERNS, [n][k]

__device__ __forceinline__ uint32_t f2tf32(float f) {
    uint32_t u;
    asm("cvt.rna.tf32.f32 %0, %1;" : "=r"(u) : "f"(f));
    return u;
}

// ---------------- init: zero outdeg counters + transpose/convert W (fused) ----------
// deg0/indeg1/indeg2 are self-cleaning: scatter's atomicSub returns them to zero.
__global__ void init_kernel(const float* __restrict__ W0, const float* __restrict__ W1) {
    int i = blockIdx.x * blockDim.x + threadIdx.x;
    if (i < ND0) g_outdeg1[i] = 0;
    if (i < ND1) g_outdeg2[i] = 0;
    if (i < DH * DH) {
        int n = i >> 7, k = i & 127;
        g_w0t[i] = __uint_as_float(f2tf32(W0[k * DH + n]));
        g_w1t[i] = __uint_as_float(f2tf32(W1[k * DH + n]));
    }
}

// ---------------- histograms ----------------
__global__ void hist_all_kernel(const int* __restrict__ src0, const int* __restrict__ dst0,
                                const int* __restrict__ src1, const int* __restrict__ dst1,
                                const int* __restrict__ src2, const int* __restrict__ dst2) {
    int i = blockIdx.x * blockDim.x + threadIdx.x;
    if (i < E0C) atomicAdd(&g_deg0[dst0[i]], 1);
    if (i < E1C) { atomicAdd(&g_indeg1[dst1[i]], 1); atomicAdd(&g_outdeg1[src1[i]], 1); }
    if (i < E2C) { atomicAdd(&g_indeg2[dst2[i]], 1); atomicAdd(&g_outdeg2[src2[i]], 1); }
}

// ---------------- multi-block scan ----------------
__device__ __forceinline__ void scan_map(int b, const int*& deg, int*& off, int*& bsum,
                                         int& n, int& cb) {
    if (b < NB0)            { deg = g_deg0;   off = g_off0; bsum = g_bsum0; n = ND0; cb = b; }
    else if (b < NB0 + NB1) { deg = g_indeg1; off = g_off1; bsum = g_bsum1; n = ND1; cb = b - NB0; }
    else                    { deg = g_indeg2; off = g_off2; bsum = g_bsum2; n = ND2; cb = b - NB0 - NB1; }
}

__global__ void scan_p1_kernel() {
    __shared__ int warp_sums[16];
    const int* deg; int* off; int* bsum; int n, cb;
    scan_map(blockIdx.x, deg, off, bsum, n, cb);
    int tid = threadIdx.x, lane = tid & 31, w = tid >> 5;
    int idx = cb * SCHUNK + tid * 4;

    int4 v = make_int4(0, 0, 0, 0);
    if (idx + 3 < n) v = *(const int4*)(deg + idx);
    else {
        if (idx     < n) v.x = deg[idx];
        if (idx + 1 < n) v.y = deg[idx + 1];
        if (idx + 2 < n) v.z = deg[idx + 2];
        if (idx + 3 < n) v.w = deg[idx + 3];
    }
    int s1 = v.x, s2 = s1 + v.y, s3 = s2 + v.z, s4 = s3 + v.w;
    int x = s4;
    #pragma unroll
    for (int d = 1; d < 32; d <<= 1) {
        int y = __shfl_up_sync(0xffffffffu, x, d);
        if (lane >= d) x += y;
    }
    if (lane == 31) warp_sums[w] = x;
    __syncthreads();
    if (w == 0 && lane < 16) {
        int s = warp_sums[lane];
        #pragma unroll
        for (int d = 1; d < 16; d <<= 1) {
            int y = __shfl_up_sync(0x0000ffffu, s, d);
            if (lane >= d) s += y;
        }
        warp_sums[lane] = s;
    }
    __syncthreads();
    int pre = (w > 0 ? warp_sums[w - 1] : 0) + (x - s4);
    if (idx     < n) off[idx]     = pre;
    if (idx + 1 < n) off[idx + 1] = pre + s1;
    if (idx + 2 < n) off[idx + 2] = pre + s2;
    if (idx + 3 < n) off[idx + 3] = pre + s3;
    if (tid == 0) bsum[cb] = warp_sums[15];
}

__global__ void scan_p2_kernel() {
    int w = threadIdx.x >> 5, lane = threadIdx.x & 31;
    int* bsum; int cnt; int* offn;
    if (w == 0)      { bsum = g_bsum0; cnt = NB0; offn = &g_off0[ND0]; }
    else if (w == 1) { bsum = g_bsum1; cnt = NB1; offn = &g_off1[ND1]; }
    else             { bsum = g_bsum2; cnt = NB2; offn = &g_off2[ND2]; }
    int v0 = (lane < cnt) ? bsum[lane] : 0;
    int v1 = (lane + 32 < cnt) ? bsum[lane + 32] : 0;
    int s0 = v0, s1v = v1;
    #pragma unroll
    for (int d = 1; d < 32; d <<= 1) {
        int y0 = __shfl_up_sync(0xffffffffu, s0, d);
        int y1 = __shfl_up_sync(0xffffffffu, s1v, d);
        if (lane >= d) { s0 += y0; s1v += y1; }
    }
    int tot0 = __shfl_sync(0xffffffffu, s0, 31);
    s1v += tot0;
    int tot = __shfl_sync(0xffffffffu, s1v, 31);
    if (lane < cnt) bsum[lane] = s0 - v0;
    if (lane + 32 < cnt) bsum[lane + 32] = s1v - v1;
    if (lane == 0) *offn = tot;
}

__global__ void scan_p3_kernel() {
    const int* deg; int* off; int* bsum; int n, cb;
    scan_map(blockIdx.x, deg, off, bsum, n, cb);
    int add = bsum[cb];
    if (add == 0) return;
    int idx = cb * SCHUNK + threadIdx.x * 4;
    if (idx + 3 < n) {
        int4 t = *(int4*)(off + idx);
        t.x += add; t.y += add; t.z += add; t.w += add;
        *(int4*)(off + idx) = t;
    } else {
        if (idx     < n) off[idx]     += add;
        if (idx + 1 < n) off[idx + 1] += add;
        if (idx + 2 < n) off[idx + 2] += add;
        if (idx + 3 < n) off[idx + 3] += add;
    }
}

// ---------------- CSR scatter ----------------
__global__ void scatter_all_kernel(const int* __restrict__ src0, const int* __restrict__ dst0,
                                   const int* __restrict__ src1, const int* __restrict__ dst1,
                                   const int* __restrict__ src2, const int* __restrict__ dst2) {
    int i = blockIdx.x * blockDim.x + threadIdx.x;
    if (i < E0C) {
        int d = dst0[i];
        int old = atomicSub(&g_deg0[d], 1);
        g_csr0[g_off0[d] + old - 1] = src0[i];
    }
    if (i < E1C) {
        int d = dst1[i];
        int old = atomicSub(&g_indeg1[d], 1);
        g_csr1[g_off1[d] + old - 1] = src1[i];
    }
    if (i < E2C) {
        int d = dst2[i];
        int old = atomicSub(&g_indeg2[d], 1);
        g_csr2[g_off2[d] + old - 1] = src2[i];
    }
}

// ---------------- layer 0 aggregation: warp per node, 4-edge unroll for MLP --------
__global__ void agg0_kernel(const float4* __restrict__ feats4) {
    int gid = blockIdx.x * blockDim.x + threadIdx.x;
    int node = gid >> 5;
    int lane = gid & 31;
    if (node >= ND0) return;
    int s = g_off0[node], e = g_off0[node + 1];
    float4 a0 = make_float4(0.f, 0.f, 0.f, 0.f);
    float4 a1 = make_float4(0.f, 0.f, 0.f, 0.f);
    float4 a2 = make_float4(0.f, 0.f, 0.f, 0.f);
    float4 a3 = make_float4(0.f, 0.f, 0.f, 0.f);
    int i = s;
    for (; i + 3 < e; i += 4) {
        int u0 = g_csr0[i], u1 = g_csr0[i + 1], u2 = g_csr0[i + 2], u3 = g_csr0[i + 3];
        float4 v0 = __ldg(&feats4[u0 * 32 + lane]);
        float4 v1 = __ldg(&feats4[u1 * 32 + lane]);
        float4 v2 = __ldg(&feats4[u2 * 32 + lane]);
        float4 v3 = __ldg(&feats4[u3 * 32 + lane]);
        a0.x += v0.x; a0.y += v0.y; a0.z += v0.z; a0.w += v0.w;
        a1.x += v1.x; a1.y += v1.y; a1.z += v1.z; a1.w += v1.w;
        a2.x += v2.x; a2.y += v2.y; a2.z += v2.z; a2.w += v2.w;
        a3.x += v3.x; a3.y += v3.y; a3.z += v3.z; a3.w += v3.w;
    }
    for (; i < e; i++) {
        int u = g_csr0[i];
        float4 v = __ldg(&feats4[u * 32 + lane]);
        a0.x += v.x; a0.y += v.y; a0.z += v.z; a0.w += v.w;
    }
    a0.x += a1.x + a2.x + a3.x;
    a0.y += a1.y + a2.y + a3.y;
    a0.z += a1.z + a2.z + a3.z;
    a0.w += a1.w + a2.w + a3.w;
    ((float4*)g_agg0)[node * 32 + lane] = a0;
}

// ---------------- layer 1 aggregation: perm-folded gather + out-degree scale --------
__global__ void agg1_kernel(const int* __restrict__ inverse_idx,
                            const int* __restrict__ shuffle_idx) {
    int gid = blockIdx.x * blockDim.x + threadIdx.x;
    int node = gid >> 5;
    int lane = gid & 31;
    if (node >= ND1) return;
    int s = g_off1[node], e = g_off1[node + 1];
    float4 acc = make_float4(0.f, 0.f, 0.f, 0.f);
    for (int i = s; i < e; i++) {
        int u = g_csr1[i];
        int row = inverse_idx[shuffle_idx[u]];
        float sc = rsqrtf(fmaxf((float)g_outdeg1[u], 1.f));
        float4 v = ((const float4*)g_h0)[row * 32 + lane];
        acc.x += v.x * sc; acc.y += v.y * sc; acc.z += v.z * sc; acc.w += v.w * sc;
    }
    ((float4*)g_agg1)[node * 32 + lane] = acc;
}

// ---------------- tf32 mma.sync GEMM: 256-row tile x [128,128] ---------------------
// D = A @ Wt^T (Wt already tf32 bits). Epilogue: relu(sc(row)*D + bias), sc: layer 1.
// smem: A 256x132 (tf32 bits) + W 128x132 = 198KB; 8 warps x 32 rows each.
#define MMPAD 132
__global__ void __launch_bounds__(256, 1) mm_tf32_kernel(const float* __restrict__ bias,
                                                         int layer) {
    extern __shared__ float sm[];
    uint32_t* As = (uint32_t*)sm;              // 256 x 132 tf32 bits
    uint32_t* Ws = (uint32_t*)(sm + 256 * MMPAD);  // 128 x 132 tf32 bits

    const float* A    = layer ? g_agg1 : g_agg0;
    float*       outp = layer ? g_h1   : g_h0;
    const float* Wt   = layer ? g_w1t  : g_w0t;
    const int   nrows = layer ? ND1 : ND0;

    int tid = threadIdx.x, wid = tid >> 5, lane = tid & 31;
    int row0 = blockIdx.x * 256;

    // stage A with tf32 conversion (zero-padded tail)
    for (int i = tid; i < 256 * 32; i += 256) {
        int r = i >> 5, c4 = i & 31;
        int row = row0 + r;
        uint4 o = make_uint4(0u, 0u, 0u, 0u);
        if (row < nrows) {
            float4 va = ((const float4*)A)[row * 32 + c4];
            o.x = f2tf32(va.x); o.y = f2tf32(va.y); o.z = f2tf32(va.z); o.w = f2tf32(va.w);
        }
        *(uint4*)(As + r * MMPAD + c4 * 4) = o;
    }
    // stage W (already tf32 bits)
    for (int i = tid; i < 128 * 32; i += 256) {
        int r = i >> 5, c4 = i & 31;
        *(uint4*)(Ws + r * MMPAD + c4 * 4) = ((const uint4*)Wt)[i];
    }
    __syncthreads();

    int rw = wid * 32;
    int q = lane >> 2, m4 = lane & 3;
    float d[16][8];
    #pragma unroll
    for (int t = 0; t < 16; t++)
        #pragma unroll
        for (int j = 0; j < 8; j++) d[t][j] = 0.f;

    for (int k = 0; k < 16; k++) {
        int kc = k * 8 + m4;
        uint32_t a0 = As[(rw + q) * MMPAD + kc];
        uint32_t a1 = As[(rw + q + 8) * MMPAD + kc];
        uint32_t a2 = As[(rw + q) * MMPAD + kc + 4];
        uint32_t a3 = As[(rw + q + 8) * MMPAD + kc + 4];
        uint32_t a4 = As[(rw + q + 16) * MMPAD + kc];
        uint32_t a5 = As[(rw + q + 24) * MMPAD + kc];
        uint32_t a6 = As[(rw + q + 16) * MMPAD + kc + 4];
        uint32_t a7 = As[(rw + q + 24) * MMPAD + kc + 4];
        #pragma unroll
        for (int t = 0; t < 16; t++) {
            uint32_t b0 = Ws[(t * 8 + q) * MMPAD + kc];
            uint32_t b1 = Ws[(t * 8 + q) * MMPAD + kc + 4];
            asm volatile(
                "mma.sync.aligned.m16n8k8.row.col.f32.tf32.tf32.f32 "
                "{%0,%1,%2,%3}, {%4,%5,%6,%7}, {%8,%9}, {%0,%1,%2,%3};"
                : "+f"(d[t][0]), "+f"(d[t][1]), "+f"(d[t][2]), "+f"(d[t][3])
                : "r"(a0), "r"(a1), "r"(a2), "r"(a3), "r"(b0), "r"(b1));
            asm volatile(
                "mma.sync.aligned.m16n8k8.row.col.f32.tf32.tf32.f32 "
                "{%0,%1,%2,%3}, {%4,%5,%6,%7}, {%8,%9}, {%0,%1,%2,%3};"
                : "+f"(d[t][4]), "+f"(d[t][5]), "+f"(d[t][6]), "+f"(d[t][7])
                : "r"(a4), "r"(a5), "r"(a6), "r"(a7), "r"(b0), "r"(b1));
        }
    }

    int rA = row0 + rw + q;
    int rB = rA + 8, rC = rA + 16, rD = rA + 24;
    float scA = 1.f, scB = 1.f, scC = 1.f, scD = 1.f;
    if (layer == 1) {
        if (rA < nrows) scA = rsqrtf(fmaxf((float)(g_off1[rA + 1] - g_off1[rA]), 1.f));
        if (rB < nrows) scB = rsqrtf(fmaxf((float)(g_off1[rB + 1] - g_off1[rB]), 1.f));
        if (rC < nrows) scC = rsqrtf(fmaxf((float)(g_off1[rC + 1] - g_off1[rC]), 1.f));
        if (rD < nrows) scD = rsqrtf(fmaxf((float)(g_off1[rD + 1] - g_off1[rD]), 1.f));
    }
    #pragma unroll
    for (int t = 0; t < 16; t++) {
        int c = t * 8 + m4 * 2;
        float bx = __ldg(&bias[c]), by = __ldg(&bias[c + 1]);
        if (rA < nrows) {
            float2 o = make_float2(fmaxf(d[t][0] * scA + bx, 0.f),
                                   fmaxf(d[t][1] * scA + by, 0.f));
            *(float2*)(outp + rA * DH + c) = o;
        }
        if (rB < nrows) {
            float2 o = make_float2(fmaxf(d[t][2] * scB + bx, 0.f),
                                   fmaxf(d[t][3] * scB + by, 0.f));
            *(float2*)(outp + rB * DH + c) = o;
        }
        if (rC < nrows) {
            float2 o = make_float2(fmaxf(d[t][4] * scC + bx, 0.f),
                                   fmaxf(d[t][5] * scC + by, 0.f));
            *(float2*)(outp + rC * DH + c) = o;
        }
        if (rD < nrows) {
            float2 o = make_float2(fmaxf(d[t][6] * scD + bx, 0.f),
                                   fmaxf(d[t][7] * scD + by, 0.f));
            *(float2*)(outp + rD * DH + c) = o;
        }
    }
}

// ---------------- fused layer 2: aggregate + [1,128]@[128,47] + b2 ------------------
// one block per dst2 node; 128 threads: thread t owns feature column t.
__global__ void agg2_out_kernel(const float* __restrict__ W2, const float* __restrict__ b2,
                                float* __restrict__ out) {
    __shared__ float row[128];
    int r = blockIdx.x;
    int t = threadIdx.x;  // 128
    int s = g_off2[r], e = g_off2[r + 1];
    float acc = 0.f;
    for (int i = s; i < e; i++) {
        int u = g_csr2[i];
        float sc = rsqrtf(fmaxf((float)g_outdeg2[u], 1.f));
        acc += g_h1[u * DH + t] * sc;
    }
    float scd = rsqrtf(fmaxf((float)(e - s), 1.f));
    row[t] = acc * scd;
    __syncthreads();
    if (t < NCLS) {
        float o = 0.f;
        #pragma unroll 8
        for (int k = 0; k < 128; k++)
            o += row[k] * __ldg(&W2[k * NCLS + t]);
        out[r * NCLS + t] = o + __ldg(&b2[t]);
    }
}

// ---------------- launch ----------------
extern "C" void kernel_launch(void* const* d_in, const int* in_sizes, int n_in,
                              void* d_out, int out_size) {
    (void)in_sizes; (void)n_in; (void)out_size;
    const float* feats       = (const float*)d_in[0];
    const int*   src0        = (const int*)d_in[1];
    const int*   dst0        = (const int*)d_in[2];
    const int*   src1        = (const int*)d_in[3];
    const int*   dst1        = (const int*)d_in[4];
    const int*   src2        = (const int*)d_in[5];
    const int*   dst2        = (const int*)d_in[6];
    const int*   inverse_idx = (const int*)d_in[7];
    const int*   shuffle_idx = (const int*)d_in[8];
    const float* W0          = (const float*)d_in[9];
    const float* b0          = (const float*)d_in[10];
    const float* W1          = (const float*)d_in[11];
    const float* b1          = (const float*)d_in[12];
    const float* W2          = (const float*)d_in[13];
    const float* b2          = (const float*)d_in[14];
    float* out = (float*)d_out;

    const int MM_SMEM = (256 + 128) * MMPAD * 4;  // 202752 bytes
    cudaFuncSetAttribute(mm_tf32_kernel,
                         cudaFuncAttributeMaxDynamicSharedMemorySize, MM_SMEM);

    init_kernel<<<(ND0 + 255) / 256, 256>>>(W0, W1);
    hist_all_kernel<<<(E0C + 255) / 256, 256>>>(src0, dst0, src1, dst1, src2, dst2);
    scan_p1_kernel<<<NBT, 512>>>();
    scan_p2_kernel<<<1, 96>>>();
    scan_p3_kernel<<<NBT, 512>>>();
    scatter_all_kernel<<<(E0C + 255) / 256, 256>>>(src0, dst0, src1, dst1, src2, dst2);

    // layer 0
    agg0_kernel<<<(ND0 * 32 + 255) / 256, 256>>>((const float4*)feats);
    mm_tf32_kernel<<<(ND0 + 255) / 256, 256, MM_SMEM>>>(b0, 0);

    // layer 1 (perm folded into gather)
    agg1_kernel<<<(ND1 * 32 + 255) / 256, 256>>>(inverse_idx, shuffle_idx);
    mm_tf32_kernel<<<(ND1 + 255) / 256, 256, MM_SMEM>>>(b1, 1);

    // layer 2 (fused aggregate + output gemv)
    agg2_out_kernel<<<ND2, 128>>>(W2, b2, out);
}